// round 11
// baseline (speedup 1.0000x reference)
#include <cuda_runtime.h>
#include <cuda_fp16.h>

#define TILE  256
#define HALO  12
#define KWIN  9
#define DIL   3
#define HD    32
#define NC2   16                 /* channel pairs */
#define KV_W  (TILE + 2*HALO)    /* 280 tokens incl. halo */
#define KV_P  284                /* padded row stride (covers special over-read) */
#define NQ4   (KV_W / 4)         /* 70 token-quads per channel-pair row */
#define NSTG  (NC2 * NQ4)        /* 1120 staging items */

typedef unsigned long long u64;
typedef unsigned int u32;

__device__ __forceinline__ u64 pack2(float a, float b) {
    u64 r; asm("mov.b64 %0, {%1, %2};" : "=l"(r) : "f"(a), "f"(b)); return r;
}
__device__ __forceinline__ void unpack2(u64 p, float& a, float& b) {
    asm("mov.b64 {%0, %1}, %2;" : "=f"(a), "=f"(b) : "l"(p));
}
__device__ __forceinline__ u64 fma2(u64 a, u64 b, u64 c) {
    u64 d; asm("fma.rn.f32x2 %0, %1, %2, %3;" : "=l"(d) : "l"(a), "l"(b), "l"(c)); return d;
}
__device__ __forceinline__ u64 h2f2(__half2 h) {
    const float2 f = __half22float2(h);
    return pack2(f.x, f.y);
}
__device__ __forceinline__ u32 h2u(__half2 h) { u32 u; *(__half2*)&u = h; return u; }
__device__ __forceinline__ __half2 u2h(u32 u) { return *(__half2*)&u; }

// bounds-checked float4 load (zero-fill OOB = Unfold padding)
__device__ __forceinline__ float4 ld4(const float* __restrict__ row, int n, int L) {
    if (n >= 0 && n + 3 < L) return *(const float4*)(row + n);
    float4 r;
    r.x = ((unsigned)(n + 0) < (unsigned)L) ? row[n + 0] : 0.f;
    r.y = ((unsigned)(n + 1) < (unsigned)L) ? row[n + 1] : 0.f;
    r.z = ((unsigned)(n + 2) < (unsigned)L) ? row[n + 2] : 0.f;
    r.w = ((unsigned)(n + 3) < (unsigned)L) ? row[n + 3] : 0.f;
    return r;
}

__device__ __forceinline__ void softmax9(float* s) {
    float mx = -1e30f;
    #pragma unroll
    for (int kk = 0; kk < KWIN; kk++) mx = fmaxf(mx, s[kk]);
    float sum = 0.f;
    #pragma unroll
    for (int kk = 0; kk < KWIN; kk++) { s[kk] = __expf(s[kk] - mx); sum += s[kk]; }
    const float inv = 1.f / sum;
    #pragma unroll
    for (int kk = 0; kk < KWIN; kk++) s[kk] *= inv;
}

__global__ __launch_bounds__(128, 6)
void dilated_attn_kernel(const float* __restrict__ q,
                         const float* __restrict__ k,
                         const float* __restrict__ v,
                         float* __restrict__ out)
{
    // half2 channel-pair layout, row stride KV_P (padded).
    __shared__ __half2 ks[NC2][KV_P];
    __shared__ __half2 vs[NC2][KV_P];

    const int j    = threadIdx.x;
    const int tile = blockIdx.x & 15;          // 4096/256 = 16 tiles
    const int h    = (blockIdx.x >> 4) & 15;   // 16 heads
    const int b    = blockIdx.x >> 8;          // 4 batches
    const int n0   = tile * TILE;
    const int L = 4096, d = 512;

    // thread -> token pair (na, nb). Pairs (x, x+3) partition the 256-token
    // tile except one leftover distance-1 pair (253,254) handled by j==127.
    const bool special = (j == 127);
    int la;
    if (j < 126)        la = (j % 3) + 6 * (j / 3);
    else if (j == 126)  la = 252;
    else                la = 253;
    const int lb = special ? 254 : la + 3;
    const int na = n0 + la;
    const int nb = n0 + lb;

    const long cb = ((long)b * d + h * HD) * L;
    const float* qb = q + cb;
    const float* kb = k + cb;
    const float* vb = v + cb;

    // ---- prefetch q for both tokens as half2 (scale folded) ----
    const float scale = 0.17677669529663687f;   // 32^-0.5
    u32 qAh[NC2], qBh[NC2];
    #pragma unroll
    for (int c2 = 0; c2 < NC2; c2++) {
        const long r0 = (long)(2 * c2 + 0) * L;
        const long r1 = (long)(2 * c2 + 1) * L;
        qAh[c2] = h2u(__floats2half2_rn(qb[r0 + na] * scale, qb[r1 + na] * scale));
        qBh[c2] = h2u(__floats2half2_rn(qb[r0 + nb] * scale, qb[r1 + nb] * scale));
    }

    // ---- stage K and V as f16 (one barrier total) ----
    #pragma unroll
    for (int it = 0; it < 9; it++) {
        const int idx = j + it * 128;
        if (idx < NSTG) {
            const int c2 = idx / NQ4;
            const int g  = idx - c2 * NQ4;
            const int ng = n0 - HALO + g * 4;
            const long r0 = (long)(2 * c2 + 0) * L;
            const long r1 = (long)(2 * c2 + 1) * L;
            const float4 ka = ld4(kb + r0, ng, L);
            const float4 kc = ld4(kb + r1, ng, L);
            const float4 va = ld4(vb + r0, ng, L);
            const float4 vc = ld4(vb + r1, ng, L);
            uint4 pk, pv;
            pk.x = h2u(__floats2half2_rn(ka.x, kc.x));
            pk.y = h2u(__floats2half2_rn(ka.y, kc.y));
            pk.z = h2u(__floats2half2_rn(ka.z, kc.z));
            pk.w = h2u(__floats2half2_rn(ka.w, kc.w));
            pv.x = h2u(__floats2half2_rn(va.x, vc.x));
            pv.y = h2u(__floats2half2_rn(va.y, vc.y));
            pv.z = h2u(__floats2half2_rn(va.z, vc.z));
            pv.w = h2u(__floats2half2_rn(va.w, vc.w));
            *(uint4*)&ks[c2][g * 4] = pk;
            *(uint4*)&vs[c2][g * 4] = pv;
        }
    }
    __syncthreads();

    // ---- QK^T for both tokens: 10 shared taps per c2 ----
    u64 accA[KWIN], accB[KWIN];
    #pragma unroll
    for (int kk = 0; kk < KWIN; kk++) { accA[kk] = 0ull; accB[kk] = 0ull; }

    #pragma unroll
    for (int c2 = 0; c2 < NC2; c2++) {
        const u64 qA = h2f2(u2h(qAh[c2]));
        const u64 qB = h2f2(u2h(qBh[c2]));
        const __half2* kr = &ks[c2][la];   // tap i at kr[3i], i=0..9
        #pragma unroll
        for (int i = 0; i <= KWIN; i++) {
            const u64 f = h2f2(kr[3 * i]);
            if (i < KWIN) accA[i]     = fma2(qA, f, accA[i]);
            if (i > 0)    accB[i - 1] = fma2(qB, f, accB[i - 1]);
        }
    }
    if (special) {   // token B is at distance 1: redo with its own taps
        #pragma unroll
        for (int kk = 0; kk < KWIN; kk++) accB[kk] = 0ull;
        #pragma unroll
        for (int c2 = 0; c2 < NC2; c2++) {
            const u64 qB = h2f2(u2h(qBh[c2]));
            const __half2* kr = &ks[c2][lb];
            #pragma unroll
            for (int kk = 0; kk < KWIN; kk++)
                accB[kk] = fma2(qB, h2f2(kr[3 * kk]), accB[kk]);
        }
    }

    // ---- softmax for both tokens ----
    float sA[KWIN], sB[KWIN];
    #pragma unroll
    for (int kk = 0; kk < KWIN; kk++) {
        float lo, hi;
        unpack2(accA[kk], lo, hi); sA[kk] = lo + hi;
        unpack2(accB[kk], lo, hi); sB[kk] = lo + hi;
    }
    softmax9(sA);
    softmax9(sB);
    u64 wA[KWIN], wB[KWIN];
    #pragma unroll
    for (int kk = 0; kk < KWIN; kk++) {
        wA[kk] = pack2(sA[kk], sA[kk]);
        wB[kk] = pack2(sB[kk], sB[kk]);
    }

    // ---- attn @ V in two channel halves (keeps registers bounded) ----
    #pragma unroll 1
    for (int half = 0; half < 2; half++) {
        u64 oA[8], oB[8];
        #pragma unroll
        for (int c = 0; c < 8; c++) { oA[c] = 0ull; oB[c] = 0ull; }

        #pragma unroll
        for (int c2h = 0; c2h < 8; c2h++) {
            const int c2 = half * 8 + c2h;
            const __half2* vr = &vs[c2][la];
            #pragma unroll
            for (int i = 0; i <= KWIN; i++) {
                const u64 vv = h2f2(vr[3 * i]);
                if (i < KWIN) oA[c2h] = fma2(wA[i], vv, oA[c2h]);
                if (i > 0)    oB[c2h] = fma2(wB[i - 1], vv, oB[c2h]);
            }
        }
        if (special) {
            #pragma unroll
            for (int c2h = 0; c2h < 8; c2h++) {
                const int c2 = half * 8 + c2h;
                oB[c2h] = 0ull;
                const __half2* vr = &vs[c2][lb];
                #pragma unroll
                for (int kk = 0; kk < KWIN; kk++)
                    oB[c2h] = fma2(wB[kk], h2f2(vr[3 * kk]), oB[c2h]);
            }
        }

        // store this half (16 channels) for both tokens
        float4* opA = (float4*)(out + ((long)b * L + na) * d + h * HD + half * 16);
        float4* opB = (float4*)(out + ((long)b * L + nb) * d + h * HD + half * 16);
        #pragma unroll
        for (int c4 = 0; c4 < 4; c4++) {
            float4 rA, rB;
            unpack2(oA[2 * c4 + 0], rA.x, rA.y);
            unpack2(oA[2 * c4 + 1], rA.z, rA.w);
            unpack2(oB[2 * c4 + 0], rB.x, rB.y);
            unpack2(oB[2 * c4 + 1], rB.z, rB.w);
            opA[c4] = rA;
            opB[c4] = rB;
        }
    }
}

extern "C" void kernel_launch(void* const* d_in, const int* in_sizes, int n_in,
                              void* d_out, int out_size)
{
    const float* q = (const float*)d_in[0];
    const float* k = (const float*)d_in[1];
    const float* v = (const float*)d_in[2];
    float* out = (float*)d_out;

    const int grid = 4 * 16 * (4096 / TILE);   // 1024
    dilated_attn_kernel<<<grid, 128>>>(q, k, v, out);
}

// round 12
// speedup vs baseline: 1.4944x; 1.4944x over previous
#include <cuda_runtime.h>
#include <cuda_fp16.h>

#define TILE  128
#define HALO  12
#define KWIN  9
#define DIL   3
#define HD    32
#define NC2   (HD / 2)          /* 16 channel pairs */
#define KV_W  (TILE + 2*HALO)   /* 152 tokens incl. halo */
#define NQ4   (KV_W / 4)        /* 38 token-quads per channel-pair row */
#define NSTG  (NC2 * NQ4)       /* 608 staging items */

typedef unsigned long long u64;
typedef unsigned int u32;

__device__ __forceinline__ u64 pack2(float a, float b) {
    u64 r; asm("mov.b64 %0, {%1, %2};" : "=l"(r) : "f"(a), "f"(b)); return r;
}
__device__ __forceinline__ void unpack2(u64 p, float& a, float& b) {
    asm("mov.b64 {%0, %1}, %2;" : "=f"(a), "=f"(b) : "l"(p));
}
__device__ __forceinline__ u64 fma2(u64 a, u64 b, u64 c) {
    u64 d; asm("fma.rn.f32x2 %0, %1, %2, %3;" : "=l"(d) : "l"(a), "l"(b), "l"(c)); return d;
}
// half2 -> packed f32x2 (u64)
__device__ __forceinline__ u64 h2f2(__half2 h) {
    const float2 f = __half22float2(h);
    return pack2(f.x, f.y);
}
__device__ __forceinline__ u32 h2u(__half2 h) { u32 u; *(__half2*)&u = h; return u; }
__device__ __forceinline__ __half2 u2h(u32 u) { return *(__half2*)&u; }

// bounds-checked float4 load (zero-fill OOB = Unfold padding)
__device__ __forceinline__ float4 ld4(const float* __restrict__ row, int n, int L) {
    if (n >= 0 && n + 3 < L) return *(const float4*)(row + n);
    float4 r;
    r.x = ((unsigned)(n + 0) < (unsigned)L) ? row[n + 0] : 0.f;
    r.y = ((unsigned)(n + 1) < (unsigned)L) ? row[n + 1] : 0.f;
    r.z = ((unsigned)(n + 2) < (unsigned)L) ? row[n + 2] : 0.f;
    r.w = ((unsigned)(n + 3) < (unsigned)L) ? row[n + 3] : 0.f;
    return r;
}

__global__ __launch_bounds__(TILE, 7)
void dilated_attn_kernel(const float* __restrict__ q,
                         const float* __restrict__ k,
                         const float* __restrict__ v,
                         float* __restrict__ out,
                         int B, int d, int L)
{
    // half2 channel-pair layout; staging STS.128 conflict-free;
    // compute LDS.32 lane-consecutive = 1 wavefront/warp-op.
    __shared__ __half2 ks[NC2][KV_W];
    __shared__ __half2 vs[NC2][KV_W];

    const int t    = threadIdx.x;
    const int tile = blockIdx.x & 31;          // L/TILE = 32
    const int h    = (blockIdx.x >> 5) & 15;   // 16 heads
    const int b    = blockIdx.x >> 9;          // 4 batches
    const int n0   = tile * TILE;
    const int n    = n0 + t;

    const long chan_base = ((long)b * d + h * HD) * L;
    const float* kb = k + chan_base;
    const float* vb = v + chan_base;
    const float* qb = q + chan_base;

    // ---- prefetch q as half2 (scale folded in); overlaps staging latency ----
    const float scale = 0.17677669529663687f;   // 32^-0.5
    u32 q2h[NC2];
    #pragma unroll
    for (int c2 = 0; c2 < NC2; c2++) {
        const float a  = qb[(long)(2 * c2 + 0) * L + n] * scale;
        const float bq = qb[(long)(2 * c2 + 1) * L + n] * scale;
        q2h[c2] = h2u(__floats2half2_rn(a, bq));
    }

    // ---- stage K and V together as f16 (one barrier total) ----
    #pragma unroll
    for (int it = 0; it < 5; it++) {
        const int idx = t + it * TILE;
        if (idx < NSTG) {
            const int c2 = idx / NQ4;
            const int g  = idx - c2 * NQ4;
            const int ng = n0 - HALO + g * 4;
            const long r0 = (long)(2 * c2 + 0) * L;
            const long r1 = (long)(2 * c2 + 1) * L;
            const float4 ka = ld4(kb + r0, ng, L);
            const float4 kc = ld4(kb + r1, ng, L);
            const float4 va = ld4(vb + r0, ng, L);
            const float4 vc = ld4(vb + r1, ng, L);
            uint4 pk, pv;
            pk.x = h2u(__floats2half2_rn(ka.x, kc.x));
            pk.y = h2u(__floats2half2_rn(ka.y, kc.y));
            pk.z = h2u(__floats2half2_rn(ka.z, kc.z));
            pk.w = h2u(__floats2half2_rn(ka.w, kc.w));
            pv.x = h2u(__floats2half2_rn(va.x, vc.x));
            pv.y = h2u(__floats2half2_rn(va.y, vc.y));
            pv.z = h2u(__floats2half2_rn(va.z, vc.z));
            pv.w = h2u(__floats2half2_rn(va.w, vc.w));
            *(uint4*)&ks[c2][g * 4] = pk;
            *(uint4*)&vs[c2][g * 4] = pv;
        }
    }
    __syncthreads();

    // ---- QK^T: half2 HFMA2 accumulation in 2 groups of 8 channels,
    //      widened to f32 between groups (no per-tap CVTs) ----
    float s[KWIN];
    #pragma unroll
    for (int kk = 0; kk < KWIN; kk++) s[kk] = 0.f;

    #pragma unroll
    for (int g = 0; g < 2; g++) {
        u32 acc_h[KWIN];
        #pragma unroll
        for (int kk = 0; kk < KWIN; kk++) acc_h[kk] = 0u;

        #pragma unroll
        for (int c2h = 0; c2h < 8; c2h++) {
            const int c2 = g * 8 + c2h;
            const __half2 qq = u2h(q2h[c2]);
            const __half2* kr = &ks[c2][t];
            #pragma unroll
            for (int kk = 0; kk < KWIN; kk++) {
                acc_h[kk] = h2u(__hfma2(qq, kr[DIL * kk], u2h(acc_h[kk])));
            }
        }
        #pragma unroll
        for (int kk = 0; kk < KWIN; kk++) {
            const float2 f = __half22float2(u2h(acc_h[kk]));
            s[kk] += f.x + f.y;
        }
    }

    // ---- softmax over 9 (scale already folded into q) ----
    float mx = -1e30f;
    #pragma unroll
    for (int kk = 0; kk < KWIN; kk++) mx = fmaxf(mx, s[kk]);
    float sum = 0.f;
    #pragma unroll
    for (int kk = 0; kk < KWIN; kk++) { s[kk] = __expf(s[kk] - mx); sum += s[kk]; }
    const float inv = 1.f / sum;
    #pragma unroll
    for (int kk = 0; kk < KWIN; kk++) s[kk] *= inv;

    // ---- attn @ V (full f32x2 precision on the output path) ----
    u64 o2[NC2];
    #pragma unroll
    for (int c2 = 0; c2 < NC2; c2++) o2[c2] = 0ull;

    #pragma unroll
    for (int kk = 0; kk < KWIN; kk++) {
        const u64 ww = pack2(s[kk], s[kk]);
        const __half2* vr = &vs[0][t + DIL * kk];
        #pragma unroll
        for (int c2 = 0; c2 < NC2; c2++) {
            o2[c2] = fma2(ww, h2f2(vr[c2 * KV_W]), o2[c2]);
        }
    }

    // ---- store: out[b][0][n][h*32+c] -> one full 128B line per thread ----
    float4* op = (float4*)(out + ((long)b * L + n) * d + h * HD);
    #pragma unroll
    for (int c4 = 0; c4 < HD / 4; c4++) {
        float4 r;
        unpack2(o2[c4 * 2 + 0], r.x, r.y);
        unpack2(o2[c4 * 2 + 1], r.z, r.w);
        op[c4] = r;
    }
}

extern "C" void kernel_launch(void* const* d_in, const int* in_sizes, int n_in,
                              void* d_out, int out_size)
{
    const float* q = (const float*)d_in[0];
    const float* k = (const float*)d_in[1];
    const float* v = (const float*)d_in[2];
    float* out = (float*)d_out;

    const int B = 4, d = 512, L = 4096;
    const int grid = B * (d / HD) * (L / TILE);   // 2048
    dilated_attn_kernel<<<grid, TILE>>>(q, k, v, out, B, d, L);
}